// round 11
// baseline (speedup 1.0000x reference)
#include <cuda_runtime.h>
#include <cuda_bf16.h>
#include <math.h>
#include <stdint.h>

#define SEQ_N 2048
#define DIM_D 512
#define NHEAD 8
#define HDIM 64
#define NOFF 47
#define N1 2048          // fused GEMM1 output width (1536 qkv + 512 gate)
#define KDIM 512

__constant__ int c_off[NOFF] = {
    0,1,2,3,4,5,6,7,8,9,10,11,12,13,14,15,16,17,18,19,20,21,22,23,24,25,26,
    27,28,29,30,31,32,48,64,96,128,192,256,384,512,768,1024,1536,2048,3072,4096
};

// Scratch
__device__ float g_qkv [SEQ_N * 3 * DIM_D];
__device__ float g_gsig[SEQ_N * DIM_D];
__device__ __align__(16) __nv_bfloat16 g_xhi [SEQ_N * DIM_D];
__device__ __align__(16) __nv_bfloat16 g_xlo [SEQ_N * DIM_D];
__device__ __align__(16) __nv_bfloat16 g_ghi [SEQ_N * DIM_D];
__device__ __align__(16) __nv_bfloat16 g_glo [SEQ_N * DIM_D];
__device__ __align__(16) __nv_bfloat16 g_w1hi[KDIM * N1];     // [k][n] (qkv|gate)
__device__ __align__(16) __nv_bfloat16 g_w1lo[KDIM * N1];
__device__ __align__(16) __nv_bfloat16 g_wohi[KDIM * DIM_D];
__device__ __align__(16) __nv_bfloat16 g_wolo[KDIM * DIM_D];

// ---------------------------------------------------------------------------
// Fused fp32 -> bf16 hi/lo split.
// float4 regions: x 262144 | W1(merged qkv+gate) 262144 | wo 65536
// ---------------------------------------------------------------------------
__device__ __forceinline__ void cvt_store(float4 v, __nv_bfloat16* hi,
                                          __nv_bfloat16* lo, int i)
{
    __nv_bfloat16 h0 = __float2bfloat16(v.x);
    __nv_bfloat16 h1 = __float2bfloat16(v.y);
    __nv_bfloat16 h2 = __float2bfloat16(v.z);
    __nv_bfloat16 h3 = __float2bfloat16(v.w);
    __nv_bfloat162 hh0 = {h0, h1}, hh1 = {h2, h3};
    ((__nv_bfloat162*)hi)[i * 2 + 0] = hh0;
    ((__nv_bfloat162*)hi)[i * 2 + 1] = hh1;
    __nv_bfloat162 ll0 = {__float2bfloat16(v.x - __bfloat162float(h0)),
                          __float2bfloat16(v.y - __bfloat162float(h1))};
    __nv_bfloat162 ll1 = {__float2bfloat16(v.z - __bfloat162float(h2)),
                          __float2bfloat16(v.w - __bfloat162float(h3))};
    ((__nv_bfloat162*)lo)[i * 2 + 0] = ll0;
    ((__nv_bfloat162*)lo)[i * 2 + 1] = ll1;
}

__global__ void __launch_bounds__(256) cvt_all_kernel(
    const float* __restrict__ x, const float* __restrict__ wqkv,
    const float* __restrict__ wg, const float* __restrict__ wo)
{
    const int i = blockIdx.x * 256 + threadIdx.x;
    if (i < 262144) {
        cvt_store(((const float4*)x)[i], g_xhi, g_xlo, i);
    } else if (i < 524288) {
        const int j = i - 262144;           // W1: row k, 512 float4 per row
        const int k = j >> 9;
        const int cc = j & 511;
        float4 v = (cc < 384) ? ((const float4*)wqkv)[k * 384 + cc]
                              : ((const float4*)wg)[k * 128 + (cc - 384)];
        cvt_store(v, g_w1hi, g_w1lo, j);
    } else if (i < 589824) {
        const int j = i - 524288;
        cvt_store(((const float4*)wo)[j], g_wohi, g_wolo, j);
    }
}

// ---------------------------------------------------------------------------
// MMA primitives
// ---------------------------------------------------------------------------
__device__ __forceinline__ uint32_t smem_u32(const void* p)
{
    return (uint32_t)__cvta_generic_to_shared(p);
}

__device__ __forceinline__ void cp16(void* dst, const void* src)
{
    asm volatile("cp.async.cg.shared.global [%0], [%1], 16;\n"
                 :: "r"(smem_u32(dst)), "l"(src));
}

__device__ __forceinline__ void ldsm_x4(uint32_t& r0, uint32_t& r1,
                                        uint32_t& r2, uint32_t& r3, uint32_t addr)
{
    asm volatile("ldmatrix.sync.aligned.m8n8.x4.shared.b16 {%0,%1,%2,%3},[%4];"
                 : "=r"(r0), "=r"(r1), "=r"(r2), "=r"(r3) : "r"(addr));
}

__device__ __forceinline__ void ldsm_x4_t(uint32_t& r0, uint32_t& r1,
                                          uint32_t& r2, uint32_t& r3, uint32_t addr)
{
    asm volatile("ldmatrix.sync.aligned.m8n8.x4.trans.shared.b16 {%0,%1,%2,%3},[%4];"
                 : "=r"(r0), "=r"(r1), "=r"(r2), "=r"(r3) : "r"(addr));
}

__device__ __forceinline__ void mma_bf16(float* c, const uint32_t* a, const uint32_t* b)
{
    asm volatile(
        "mma.sync.aligned.m16n8k16.row.col.f32.bf16.bf16.f32 "
        "{%0,%1,%2,%3},{%4,%5,%6,%7},{%8,%9},{%0,%1,%2,%3};"
        : "+f"(c[0]), "+f"(c[1]), "+f"(c[2]), "+f"(c[3])
        : "r"(a[0]), "r"(a[1]), "r"(a[2]), "r"(a[3]), "r"(b[0]), "r"(b[1]));
}

// ---------------------------------------------------------------------------
// GEMM2 body (exactly the R7 passing kernel): 64x64 tile, GBK=32, 256 thr
// (8 warps 4x2, warp tile 16x32), 2-stage. EPI 0: C = acc + bias (fp32).
// ---------------------------------------------------------------------------
#define GBM 64
#define GBN 64
#define GBK 32
#define ASTR 40
#define BSTR 72

__global__ void __launch_bounds__(256) gemm2_kernel(
    const float* __restrict__ bias1, float* __restrict__ Cout)
{
    const __nv_bfloat16* Ahi = g_ghi;
    const __nv_bfloat16* Alo = g_glo;
    const __nv_bfloat16* Bhi = g_wohi;
    const __nv_bfloat16* Blo = g_wolo;
    const int N = DIM_D, K = KDIM;

    __shared__ __nv_bfloat16 sA[2][2][GBM][ASTR];
    __shared__ __nv_bfloat16 sB[2][2][GBK][BSTR];

    const int tid  = threadIdx.x;
    const int lane = tid & 31;
    const int warp = tid >> 5;
    const int wm = warp >> 1, wn = warp & 1;     // 4 x 2
    const int brow = blockIdx.y * GBM;
    const int bcol = blockIdx.x * GBN;

    float acc[4][4];
    #pragma unroll
    for (int j = 0; j < 4; j++)
        #pragma unroll
        for (int t = 0; t < 4; t++) acc[j][t] = 0.f;

    auto load_stage = [&](int s, int k0) {
        #pragma unroll
        for (int i = 0; i < 2; i++) {            // A: 512 chunks, 2/thread
            const int c   = tid + i * 256;
            const int mat = c >> 8;
            const int rem = c & 255;
            const int row = rem >> 2;
            const int kc  = (rem & 3) * 8;
            const __nv_bfloat16* src = (mat ? Alo : Ahi) + (size_t)(brow + row) * K + k0 + kc;
            cp16(&sA[s][mat][row][kc], src);
        }
        #pragma unroll
        for (int i = 0; i < 2; i++) {            // B: 512 chunks, 2/thread
            const int c   = tid + i * 256;
            const int mat = c >> 8;
            const int rem = c & 255;
            const int row = rem >> 3;
            const int col = (rem & 7) * 8;
            const __nv_bfloat16* src = (mat ? Blo : Bhi) + (size_t)(k0 + row) * N + bcol + col;
            cp16(&sB[s][mat][row][col], src);
        }
        asm volatile("cp.async.commit_group;\n" ::);
    };

    load_stage(0, 0);
    int stage = 0;
    for (int k0 = 0; k0 < K; k0 += GBK) {
        if (k0 + GBK < K) {
            load_stage(stage ^ 1, k0 + GBK);
            asm volatile("cp.async.wait_group 1;\n" ::);
        } else {
            asm volatile("cp.async.wait_group 0;\n" ::);
        }
        __syncthreads();

        #pragma unroll
        for (int kk = 0; kk < GBK; kk += 16) {
            uint32_t ahi[4], alo[4], bhi[4][2], blo[4][2];
            const int row = wm * 16 + (lane & 15);
            const int kof = kk + (lane >> 4) * 8;
            ldsm_x4(ahi[0], ahi[1], ahi[2], ahi[3], smem_u32(&sA[stage][0][row][kof]));
            ldsm_x4(alo[0], alo[1], alo[2], alo[3], smem_u32(&sA[stage][1][row][kof]));
            #pragma unroll
            for (int np = 0; np < 2; np++) {
                const int krow = kk + (lane & 15);
                const int col  = wn * 32 + np * 16 + (lane >> 4) * 8;
                ldsm_x4_t(bhi[np*2][0], bhi[np*2][1], bhi[np*2+1][0], bhi[np*2+1][1],
                          smem_u32(&sB[stage][0][krow][col]));
                ldsm_x4_t(blo[np*2][0], blo[np*2][1], blo[np*2+1][0], blo[np*2+1][1],
                          smem_u32(&sB[stage][1][krow][col]));
            }
            #pragma unroll
            for (int nt = 0; nt < 4; nt++) {
                mma_bf16(acc[nt], ahi, bhi[nt]);
                mma_bf16(acc[nt], ahi, blo[nt]);
                mma_bf16(acc[nt], alo, bhi[nt]);
            }
        }
        __syncthreads();
        stage ^= 1;
    }

    const int gid = lane >> 2, tig = lane & 3;
    #pragma unroll
    for (int nt = 0; nt < 4; nt++) {
        const int row = brow + wm * 16 + gid;
        const int col = bcol + wn * 32 + nt * 8 + tig * 2;
        const float b0 = bias1[col], b1 = bias1[col + 1];
        float2 r0 = {acc[nt][0] + b0, acc[nt][1] + b1};
        float2 r1 = {acc[nt][2] + b0, acc[nt][3] + b1};
        *(float2*)(Cout + (size_t)row * N + col)       = r0;
        *(float2*)(Cout + (size_t)(row + 8) * N + col) = r1;
    }
}

// ---------------------------------------------------------------------------
// GEMM1 (new, high-density): CTA 64x128, BK=16, 2-stage, static smem 29696B.
// 8 warps as 2x4 (wm rows, wn cols); warp tile 32x32 with MT=2 m-tiles
// (the proven R5/R6 multi-m-tile pattern). Per k16: 8 ldsm -> 24 MMAs.
// Epilogue: cols < 1536 -> g_qkv + b_qkv ; cols >= 1536 -> sigmoid -> g_gsig
// ---------------------------------------------------------------------------
#define G1TM 64
#define G1TN 128
#define G1BK 16
#define G1ASTR 24    // 16 + 8 pad (48B rows)
#define G1BSTR 136   // 128 + 8 pad (272B rows)

__global__ void __launch_bounds__(256) gemm1_kernel(
    const float* __restrict__ b_qkv, const float* __restrict__ b_gate)
{
    __shared__ __nv_bfloat16 sA[2][2][G1TM][G1ASTR];   // 12288 B
    __shared__ __nv_bfloat16 sB[2][2][G1BK][G1BSTR];   // 17408 B

    const int tid  = threadIdx.x;
    const int lane = tid & 31;
    const int warp = tid >> 5;
    const int wm = warp >> 2;                   // 0..1 (rows)
    const int wn = warp & 3;                    // 0..3 (cols)
    const int brow = blockIdx.y * G1TM;
    const int bcol = blockIdx.x * G1TN;

    float acc[2][4][4];
    #pragma unroll
    for (int i = 0; i < 2; i++)
        #pragma unroll
        for (int j = 0; j < 4; j++)
            #pragma unroll
            for (int t = 0; t < 4; t++) acc[i][j][t] = 0.f;

    auto load_stage = [&](int s, int k0) {
        // A: 256 chunks (2 mats x 64 rows x 2 k-chunks), 1 per thread
        {
            const int mat = tid >> 7;
            const int rem = tid & 127;
            const int row = rem >> 1;
            const int kc  = (rem & 1) * 8;
            const __nv_bfloat16* src =
                (mat ? g_xlo : g_xhi) + (size_t)(brow + row) * KDIM + k0 + kc;
            cp16(&sA[s][mat][row][kc], src);
        }
        // B: 512 chunks (2 mats x 16 rows x 16 col-chunks), 2 per thread
        #pragma unroll
        for (int i = 0; i < 2; i++) {
            const int c   = tid + i * 256;
            const int mat = c >> 8;
            const int rem = c & 255;
            const int row = rem >> 4;
            const int col = (rem & 15) * 8;
            const __nv_bfloat16* src =
                (mat ? g_w1lo : g_w1hi) + (size_t)(k0 + row) * N1 + bcol + col;
            cp16(&sB[s][mat][row][col], src);
        }
        asm volatile("cp.async.commit_group;\n" ::);
    };

    constexpr int NIT = KDIM / G1BK;   // 32
    load_stage(0, 0);
    int stage = 0;
    for (int it = 0; it < NIT; it++) {
        if (it + 1 < NIT) {
            load_stage(stage ^ 1, (it + 1) * G1BK);
            asm volatile("cp.async.wait_group 1;\n" ::);
        } else {
            asm volatile("cp.async.wait_group 0;\n" ::);
        }
        __syncthreads();

        uint32_t ahi[2][4], alo[2][4], bhi[4][2], blo[4][2];
        #pragma unroll
        for (int mt = 0; mt < 2; mt++) {
            const int row = wm * 32 + mt * 16 + (lane & 15);
            const int kof = (lane >> 4) * 8;
            ldsm_x4(ahi[mt][0], ahi[mt][1], ahi[mt][2], ahi[mt][3],
                    smem_u32(&sA[stage][0][row][kof]));
            ldsm_x4(alo[mt][0], alo[mt][1], alo[mt][2], alo[mt][3],
                    smem_u32(&sA[stage][1][row][kof]));
        }
        #pragma unroll
        for (int np = 0; np < 2; np++) {
            const int krow = lane & 15;
            const int col  = wn * 32 + np * 16 + (lane >> 4) * 8;
            ldsm_x4_t(bhi[np*2][0], bhi[np*2][1], bhi[np*2+1][0], bhi[np*2+1][1],
                      smem_u32(&sB[stage][0][krow][col]));
            ldsm_x4_t(blo[np*2][0], blo[np*2][1], blo[np*2+1][0], blo[np*2+1][1],
                      smem_u32(&sB[stage][1][krow][col]));
        }
        #pragma unroll
        for (int mt = 0; mt < 2; mt++)
            #pragma unroll
            for (int nt = 0; nt < 4; nt++) {
                mma_bf16(acc[mt][nt], ahi[mt], bhi[nt]);
                mma_bf16(acc[mt][nt], ahi[mt], blo[nt]);
                mma_bf16(acc[mt][nt], alo[mt], bhi[nt]);
            }
        __syncthreads();
        stage ^= 1;
    }

    // epilogue (tile is column-uniform: bcol multiples of 128; gate at >=1536)
    const int gid = lane >> 2, tig = lane & 3;
    #pragma unroll
    for (int mt = 0; mt < 2; mt++) {
        #pragma unroll
        for (int nt = 0; nt < 4; nt++) {
            const int row = brow + wm * 32 + mt * 16 + gid;
            const int col = bcol + wn * 32 + nt * 8 + tig * 2;
            if (bcol < 3 * DIM_D) {
                const float b0 = b_qkv[col], b1 = b_qkv[col + 1];
                float2 r0 = {acc[mt][nt][0] + b0, acc[mt][nt][1] + b1};
                float2 r1 = {acc[mt][nt][2] + b0, acc[mt][nt][3] + b1};
                float* qp = (float*)g_qkv;
                *(float2*)(qp + (size_t)row * (3 * DIM_D) + col)       = r0;
                *(float2*)(qp + (size_t)(row + 8) * (3 * DIM_D) + col) = r1;
            } else {
                const int gc = col - 3 * DIM_D;
                const float b0 = b_gate[gc], b1 = b_gate[gc + 1];
                float2 r0, r1;
                r0.x = 1.f / (1.f + __expf(-(acc[mt][nt][0] + b0)));
                r0.y = 1.f / (1.f + __expf(-(acc[mt][nt][1] + b1)));
                r1.x = 1.f / (1.f + __expf(-(acc[mt][nt][2] + b0)));
                r1.y = 1.f / (1.f + __expf(-(acc[mt][nt][3] + b1)));
                float* gs = (float*)g_gsig;
                *(float2*)(gs + (size_t)row * DIM_D + gc)       = r0;
                *(float2*)(gs + (size_t)(row + 8) * DIM_D + gc) = r1;
            }
        }
    }
}

// ---------------------------------------------------------------------------
// Attention + gating: one warp per (n, h); writes gated bf16 hi/lo.
// ---------------------------------------------------------------------------
__global__ void __launch_bounds__(256) attn_kernel(
    const float* __restrict__ pos_bias,
    const float* __restrict__ scale_embed,
    const float* __restrict__ if_gain,
    const float* __restrict__ disp_amp)
{
    const float* qkv = (const float*)g_qkv;
    const int warp = threadIdx.x >> 5;
    const int lane = threadIdx.x & 31;
    const int n = blockIdx.x * 8 + warp;
    const int h = blockIdx.y;
    const int d0 = lane * 2;

    const float* qrow = qkv + (size_t)n * (3 * DIM_D) + h * HDIM;
    float2 q = *(const float2*)(qrow + d0);
    q.x *= 0.125f;
    q.y *= 0.125f;

    const float LM    = logf(4097.0f);
    const float wbase = 3.14159265358979f / LM;
    const float om = (h < 2) ? 0.f : (h < 4) ? wbase : (h < 6) ? 4.f * wbase : 6.f * wbase;
    const float da = disp_amp[h];

    float eb0, eb1 = 0.f;
    {
        const int o = lane;
        float ck = (om > 0.f) ? cosf(om * logf(1.f + (float)c_off[o])) : 0.f;
        eb0 = pos_bias[o * NHEAD + h] + ck * da;
        const int o2 = lane + 32;
        if (o2 < NOFF) {
            float ck2 = (om > 0.f) ? cosf(om * logf(1.f + (float)c_off[o2])) : 0.f;
            eb1 = pos_bias[o2 * NHEAD + h] + ck2 * da;
        }
    }

    float s0 = -INFINITY, s1 = -INFINITY;

    for (int o = 0; o < NOFF; o++) {
        const int j = n - c_off[o];
        if (j < 0) break;
        const float* krow = qkv + (size_t)j * (3 * DIM_D) + DIM_D + h * HDIM;
        float2 kv = *(const float2*)(krow + d0);
        float2 se = *(const float2*)(scale_embed + o * HDIM + d0);
        float p = q.x * kv.x * (1.f + se.x) + q.y * kv.y * (1.f + se.y);
        p += __shfl_xor_sync(0xffffffffu, p, 16);
        p += __shfl_xor_sync(0xffffffffu, p, 8);
        p += __shfl_xor_sync(0xffffffffu, p, 4);
        p += __shfl_xor_sync(0xffffffffu, p, 2);
        p += __shfl_xor_sync(0xffffffffu, p, 1);
        if (o < 32) { if (lane == o)      s0 = p + eb0; }
        else        { if (lane == o - 32) s1 = p + eb1; }
    }

    float m = fmaxf(s0, s1);
    m = fmaxf(m, __shfl_xor_sync(0xffffffffu, m, 16));
    m = fmaxf(m, __shfl_xor_sync(0xffffffffu, m, 8));
    m = fmaxf(m, __shfl_xor_sync(0xffffffffu, m, 4));
    m = fmaxf(m, __shfl_xor_sync(0xffffffffu, m, 2));
    m = fmaxf(m, __shfl_xor_sync(0xffffffffu, m, 1));

    float e0 = __expf(s0 - m);
    float e1 = __expf(s1 - m);
    float z = e0 + e1;
    z += __shfl_xor_sync(0xffffffffu, z, 16);
    z += __shfl_xor_sync(0xffffffffu, z, 8);
    z += __shfl_xor_sync(0xffffffffu, z, 4);
    z += __shfl_xor_sync(0xffffffffu, z, 2);
    z += __shfl_xor_sync(0xffffffffu, z, 1);
    const float inv = 1.f / z;
    const float p0 = e0 * inv;
    const float p1 = e1 * inv;

    float2 acc = {0.f, 0.f};
    for (int o = 0; o < NOFF; o++) {
        const int j = n - c_off[o];
        if (j < 0) break;
        const float w = __shfl_sync(0xffffffffu, (o < 32) ? p0 : p1, o & 31);
        const float* vrow = qkv + (size_t)j * (3 * DIM_D) + 2 * DIM_D + h * HDIM;
        float2 vv = *(const float2*)(vrow + d0);
        acc.x = fmaf(w, vv.x, acc.x);
        acc.y = fmaf(w, vv.y, acc.y);
    }

    const float g = if_gain[h];
    const size_t oidx = (size_t)n * DIM_D + h * HDIM + d0;
    float2 gs = *(const float2*)((const float*)g_gsig + oidx);
    float v0 = acc.x * g * gs.x;
    float v1 = acc.y * g * gs.y;

    __nv_bfloat16 h0 = __float2bfloat16(v0);
    __nv_bfloat16 h1 = __float2bfloat16(v1);
    __nv_bfloat162 hv = {h0, h1};
    __nv_bfloat162 lv = {__float2bfloat16(v0 - __bfloat162float(h0)),
                         __float2bfloat16(v1 - __bfloat162float(h1))};
    *(__nv_bfloat162*)((__nv_bfloat16*)g_ghi + oidx) = hv;
    *(__nv_bfloat162*)((__nv_bfloat16*)g_glo + oidx) = lv;
}

// ---------------------------------------------------------------------------
extern "C" void kernel_launch(void* const* d_in, const int* in_sizes, int n_in,
                              void* d_out, int out_size)
{
    const float* x        = (const float*)d_in[0];
    const float* W_qkv    = (const float*)d_in[1];
    const float* b_qkv    = (const float*)d_in[2];
    const float* W_out    = (const float*)d_in[3];
    const float* b_out    = (const float*)d_in[4];
    const float* W_gate   = (const float*)d_in[5];
    const float* b_gate   = (const float*)d_in[6];
    const float* pos_bias = (const float*)d_in[7];
    const float* scale_e  = (const float*)d_in[8];
    const float* if_gain  = (const float*)d_in[9];
    const float* disp_amp = (const float*)d_in[10];
    float* out = (float*)d_out;

    cvt_all_kernel<<<2304, 256>>>(x, W_qkv, W_gate, W_out);

    {   // gemm1: x @ [Wqkv|Wgate] -> g_qkv (+bias) and g_gsig (sigmoid)
        dim3 grid(N1 / G1TN, SEQ_N / G1TM);        // 16 x 32 = 512 CTAs
        gemm1_kernel<<<grid, 256>>>(b_qkv, b_gate);
    }
    {
        dim3 grid(SEQ_N / 8, NHEAD);
        attn_kernel<<<grid, 256>>>(pos_bias, scale_e, if_gain, disp_amp);
    }
    {   // gemm2: gated @ Wout + b_out -> out
        dim3 grid(DIM_D / GBN, SEQ_N / GBM);       // 8 x 32 = 256 CTAs
        gemm2_kernel<<<grid, 256>>>(b_out, out);
    }
}